// round 15
// baseline (speedup 1.0000x reference)
#include <cuda_runtime.h>
#include <cuda_fp16.h>

#define H 128
#define NMAX 100000
#define SCAN_BLK 256

// Scratch (alloc-free rule: __device__ globals)
static __device__ float  gS[(size_t)NMAX * H];
static __device__ float  gI[(size_t)NMAX * H];
static __device__ __half gIh[(size_t)NMAX * H];  // fp16 copy of I for gathers
static __device__ float  gWt[H * H];     // W transposed
static __device__ int    gCnt[NMAX];     // per-row edge count
static __device__ int    gStart[NMAX];   // CSR row starts
static __device__ int    gCursor[NMAX];  // scatter cursors
static __device__ int    gBsum[512];     // per-scan-block partial sums
static __device__ int    gBoff[512];     // exclusive-scanned partials
static __device__ int    gPermCol[1700000]; // cols permuted into CSR order

typedef unsigned long long ull;
typedef long long ll;

__device__ __forceinline__ ull pack2(float lo, float hi) {
    ull r; asm("mov.b64 %0, {%1, %2};" : "=l"(r) : "f"(lo), "f"(hi)); return r;
}
__device__ __forceinline__ float2 unpack2(ull v) {
    float2 f; asm("mov.b64 {%0, %1}, %2;" : "=f"(f.x), "=f"(f.y) : "l"(v)); return f;
}
__device__ __forceinline__ ull fma2(ull a, ull b, ull c) {
    ull d; asm("fma.rn.f32x2 %0, %1, %2, %3;" : "=l"(d) : "l"(a), "l"(b), "l"(c)); return d;
}

__device__ __forceinline__ bool idx_is64(const int* r32, const int* c32) {
    // int64 little-endian with values < 2^31: all odd 32-bit words are 0
    return ((r32[1] | r32[3] | r32[5] | c32[1] | c32[3] | c32[5]) == 0);
}

// ---------------------------------------------------------------------------
// Kernel 0: transpose W (128x128) into gWt.
// ---------------------------------------------------------------------------
__global__ void transpose_kernel(const float* __restrict__ W)
{
    __shared__ float tile[32][33];
    int bx = blockIdx.x, by = blockIdx.y;
    int tx = threadIdx.x, ty = threadIdx.y;    // block (32, 8)
    #pragma unroll
    for (int j = 0; j < 4; j++)
        tile[ty + j * 8][tx] = W[(by * 32 + ty + j * 8) * H + bx * 32 + tx];
    __syncthreads();
    #pragma unroll
    for (int j = 0; j < 4; j++)
        gWt[(bx * 32 + ty + j * 8) * H + by * 32 + tx] = tile[tx][ty + j * 8];
}

// ---------------------------------------------------------------------------
// Kernel 1: S = sigmoid(x0 @ W^T + b), I = sigmoid(x1 @ W^T + b).
// Also writes fp16 copy of I (gIh) for the gather phase.
// ---------------------------------------------------------------------------
__global__ __launch_bounds__(256, 3) void gemm_sig_kernel(
    const float* __restrict__ x, const float* __restrict__ b, int N)
{
    __shared__ ull xs[32 * H];      // xs[nl*128 + h] = pack(x0[n][h], x1[n][h])

    const int t   = threadIdx.x;
    const int blk = blockIdx.x;
    const ll  NH  = (ll)N * H;

    const int n0 = blk * 32;
    #pragma unroll
    for (int it = 0; it < 4; it++) {
        int idx = t + it * 256;
        int nl = idx >> 5, hq = idx & 31;
        int n = n0 + nl;
        float4 a0 = make_float4(0.f, 0.f, 0.f, 0.f), a1 = a0;
        if (n < N) {
            a0 = *(const float4*)(x + (ll)n * H + hq * 4);
            a1 = *(const float4*)(x + NH + (ll)n * H + hq * 4);
        }
        ull* dst = xs + nl * H + hq * 4;
        dst[0] = pack2(a0.x, a1.x);
        dst[1] = pack2(a0.y, a1.y);
        dst[2] = pack2(a0.z, a1.z);
        dst[3] = pack2(a0.w, a1.w);
    }
    __syncthreads();

    const int to = t & 31;   // output quad: o = 4*to + i
    const int wg = t >> 5;   // node: n = n0 + wg + 8*j

    ull acc[4][4];
    {
        float4 bv = __ldg((const float4*)b + to);
        #pragma unroll
        for (int j = 0; j < 4; j++) {
            acc[j][0] = pack2(bv.x, bv.x);
            acc[j][1] = pack2(bv.y, bv.y);
            acc[j][2] = pack2(bv.z, bv.z);
            acc[j][3] = pack2(bv.w, bv.w);
        }
    }

    const ull* x0p = xs + (wg +  0) * H;
    const ull* x1p = xs + (wg +  8) * H;
    const ull* x2p = xs + (wg + 16) * H;
    const ull* x3p = xs + (wg + 24) * H;
    const float4* wt4 = (const float4*)gWt;

    #pragma unroll 4
    for (int h = 0; h < H; h++) {
        float4 w = __ldg(wt4 + h * 32 + to);
        ull w2[4];
        w2[0] = pack2(w.x, w.x); w2[1] = pack2(w.y, w.y);
        w2[2] = pack2(w.z, w.z); w2[3] = pack2(w.w, w.w);
        ull a0 = x0p[h], a1 = x1p[h], a2 = x2p[h], a3 = x3p[h];
        #pragma unroll
        for (int i = 0; i < 4; i++) {
            acc[0][i] = fma2(a0, w2[i], acc[0][i]);
            acc[1][i] = fma2(a1, w2[i], acc[1][i]);
            acc[2][i] = fma2(a2, w2[i], acc[2][i]);
            acc[3][i] = fma2(a3, w2[i], acc[3][i]);
        }
    }

    #pragma unroll
    for (int j = 0; j < 4; j++) {
        int n = n0 + wg + 8 * j;
        if (n >= N) continue;
        ll rb = (ll)n * H + 4 * to;
        float4 Sv, Iv;
        float2 z0 = unpack2(acc[j][0]);
        float2 z1 = unpack2(acc[j][1]);
        float2 z2 = unpack2(acc[j][2]);
        float2 z3 = unpack2(acc[j][3]);
        Sv.x = 1.f / (1.f + __expf(-z0.x));  Iv.x = 1.f / (1.f + __expf(-z0.y));
        Sv.y = 1.f / (1.f + __expf(-z1.x));  Iv.y = 1.f / (1.f + __expf(-z1.y));
        Sv.z = 1.f / (1.f + __expf(-z2.x));  Iv.z = 1.f / (1.f + __expf(-z2.y));
        Sv.w = 1.f / (1.f + __expf(-z3.x));  Iv.w = 1.f / (1.f + __expf(-z3.y));
        *(float4*)(gS + rb) = Sv;
        *(float4*)(gI + rb) = Iv;
        __half2 p0 = __floats2half2_rn(Iv.x, Iv.y);
        __half2 p1 = __floats2half2_rn(Iv.z, Iv.w);
        uint2 ph;
        ph.x = *(unsigned*)&p0;
        ph.y = *(unsigned*)&p1;
        *(uint2*)(gIh + rb) = ph;
    }
}

// ---------------------------------------------------------------------------
// Counting sort of edges by row (CSR build, rebuilt every call).
// ---------------------------------------------------------------------------
__global__ void zero_cnt_kernel(int N4)   // N4 = ceil(N/4)
{
    int i = blockIdx.x * blockDim.x + threadIdx.x;
    if (i < N4) ((int4*)gCnt)[i] = make_int4(0, 0, 0, 0);
}

__global__ __launch_bounds__(256) void hist_kernel(
    const void* __restrict__ rows_raw, const void* __restrict__ cols_raw, ll NE)
{
    const int* r32 = (const int*)rows_raw;
    const ll*  r64 = (const ll*)rows_raw;
    const bool is64 = idx_is64(r32, (const int*)cols_raw);
    ll tid = (ll)blockIdx.x * blockDim.x + threadIdx.x;
    ll stride = (ll)gridDim.x * blockDim.x;
    if (is64) {
        ll nv = NE >> 1;  // longlong2 chunks
        const longlong2* rv = (const longlong2*)r64;
        for (ll i = tid; i < nv; i += stride) {
            longlong2 v = __ldg(rv + i);
            atomicAdd(&gCnt[(int)v.x], 1);
            atomicAdd(&gCnt[(int)v.y], 1);
        }
        for (ll e = (nv << 1) + tid; e < NE; e += stride)
            atomicAdd(&gCnt[(int)__ldg(r64 + e)], 1);
    } else {
        ll nv = NE >> 2;  // int4 chunks
        const int4* rv = (const int4*)r32;
        for (ll i = tid; i < nv; i += stride) {
            int4 v = __ldg(rv + i);
            atomicAdd(&gCnt[v.x], 1);
            atomicAdd(&gCnt[v.y], 1);
            atomicAdd(&gCnt[v.z], 1);
            atomicAdd(&gCnt[v.w], 1);
        }
        for (ll e = (nv << 2) + tid; e < NE; e += stride)
            atomicAdd(&gCnt[__ldg(r32 + e)], 1);
    }
}

// scanA: per-block (256 elems) sum of gCnt -> gBsum
__global__ void scanA_kernel(int N)
{
    __shared__ int sh[SCAN_BLK];
    int i = blockIdx.x * SCAN_BLK + threadIdx.x;
    int v = (i < N) ? gCnt[i] : 0;
    sh[threadIdx.x] = v;
    __syncthreads();
    for (int s = SCAN_BLK / 2; s > 0; s >>= 1) {
        if (threadIdx.x < s) sh[threadIdx.x] += sh[threadIdx.x + s];
        __syncthreads();
    }
    if (threadIdx.x == 0) gBsum[blockIdx.x] = sh[0];
}

// scanB: single block exclusive scan of NB partials
__global__ void scanB_kernel(int NB)
{
    __shared__ int sh[512];
    int t = threadIdx.x;
    sh[t] = (t < NB) ? gBsum[t] : 0;
    __syncthreads();
    for (int d = 1; d < 512; d <<= 1) {
        int v = (t >= d) ? sh[t - d] : 0;
        __syncthreads();
        sh[t] += v;
        __syncthreads();
    }
    if (t < NB) gBoff[t] = sh[t] - gBsum[t];  // exclusive
}

// scanC: per-element exclusive scan within block + block offset
__global__ void scanC_kernel(int N)
{
    __shared__ int sh[SCAN_BLK];
    int t = threadIdx.x;
    int i = blockIdx.x * SCAN_BLK + t;
    int v = (i < N) ? gCnt[i] : 0;
    sh[t] = v;
    __syncthreads();
    for (int d = 1; d < SCAN_BLK; d <<= 1) {
        int u = (t >= d) ? sh[t - d] : 0;
        __syncthreads();
        sh[t] += u;
        __syncthreads();
    }
    if (i < N) {
        int ex = sh[t] - v + gBoff[blockIdx.x];
        gStart[i]  = ex;
        gCursor[i] = ex;
    }
}

__global__ __launch_bounds__(256) void scatter_kernel(
    const void* __restrict__ rows_raw, const void* __restrict__ cols_raw, ll NE)
{
    const int* r32 = (const int*)rows_raw;
    const int* c32 = (const int*)cols_raw;
    const ll*  r64 = (const ll*)rows_raw;
    const ll*  c64 = (const ll*)cols_raw;
    const bool is64 = idx_is64(r32, c32);
    ll tid = (ll)blockIdx.x * blockDim.x + threadIdx.x;
    ll stride = (ll)gridDim.x * blockDim.x;
    if (is64) {
        ll nv = NE >> 1;
        const longlong2* rv = (const longlong2*)r64;
        const longlong2* cv = (const longlong2*)c64;
        for (ll i = tid; i < nv; i += stride) {
            longlong2 r = __ldg(rv + i);
            longlong2 c = __ldg(cv + i);
            gPermCol[atomicAdd(&gCursor[(int)r.x], 1)] = (int)c.x;
            gPermCol[atomicAdd(&gCursor[(int)r.y], 1)] = (int)c.y;
        }
        for (ll e = (nv << 1) + tid; e < NE; e += stride)
            gPermCol[atomicAdd(&gCursor[(int)__ldg(r64 + e)], 1)] = (int)__ldg(c64 + e);
    } else {
        ll nv = NE >> 2;
        const int4* rv = (const int4*)r32;
        const int4* cv = (const int4*)c32;
        for (ll i = tid; i < nv; i += stride) {
            int4 r = __ldg(rv + i);
            int4 c = __ldg(cv + i);
            gPermCol[atomicAdd(&gCursor[r.x], 1)] = c.x;
            gPermCol[atomicAdd(&gCursor[r.y], 1)] = c.y;
            gPermCol[atomicAdd(&gCursor[r.z], 1)] = c.z;
            gPermCol[atomicAdd(&gCursor[r.w], 1)] = c.w;
        }
        for (ll e = (nv << 2) + tid; e < NE; e += stride)
            gPermCol[atomicAdd(&gCursor[__ldg(r32 + e)], 1)] = __ldg(c32 + e);
    }
}

// ---------------------------------------------------------------------------
// Fused gather + epilogue.  Warp per row r:
//   AI = sum_{e in CSR[r]} Ih[col[e]]  (fp16 gather, fp32 accumulate)
// Unroll x4 with 4 independent accumulators: 4 gathers in flight per warp
// (L2-latency-bound phase; MLP 2 -> 4).
//   dS = -beta*AI*S; dI = -dS - gamma*I; dR = gamma*I; out[3] = 0.
// ---------------------------------------------------------------------------
__global__ __launch_bounds__(256) void gather_epi_kernel(
    const float* __restrict__ x, float* __restrict__ out, int N)
{
    int warp = (blockIdx.x * 256 + threadIdx.x) >> 5;
    int lane = threadIdx.x & 31;
    if (warp >= N) return;
    const int r = warp;

    int start = gStart[r];
    int end   = start + gCnt[r];

    // lane handles values [lane*4, lane*4+4): 8 bytes of fp16 per row
    const __half* Ih = gIh;
    float4 a0 = make_float4(0.f, 0.f, 0.f, 0.f);
    float4 a1 = a0, a2 = a0, a3 = a0;

    int e = start;
    for (; e + 3 < end; e += 4) {
        int c0 = gPermCol[e];
        int c1 = gPermCol[e + 1];
        int c2 = gPermCol[e + 2];
        int c3 = gPermCol[e + 3];
        uint2 u0 = *(const uint2*)(Ih + (ll)c0 * H + lane * 4);
        uint2 u1 = *(const uint2*)(Ih + (ll)c1 * H + lane * 4);
        uint2 u2 = *(const uint2*)(Ih + (ll)c2 * H + lane * 4);
        uint2 u3 = *(const uint2*)(Ih + (ll)c3 * H + lane * 4);
        float2 f0a = __half22float2(*(__half2*)&u0.x);
        float2 f0b = __half22float2(*(__half2*)&u0.y);
        float2 f1a = __half22float2(*(__half2*)&u1.x);
        float2 f1b = __half22float2(*(__half2*)&u1.y);
        float2 f2a = __half22float2(*(__half2*)&u2.x);
        float2 f2b = __half22float2(*(__half2*)&u2.y);
        float2 f3a = __half22float2(*(__half2*)&u3.x);
        float2 f3b = __half22float2(*(__half2*)&u3.y);
        a0.x += f0a.x; a0.y += f0a.y; a0.z += f0b.x; a0.w += f0b.y;
        a1.x += f1a.x; a1.y += f1a.y; a1.z += f1b.x; a1.w += f1b.y;
        a2.x += f2a.x; a2.y += f2a.y; a2.z += f2b.x; a2.w += f2b.y;
        a3.x += f3a.x; a3.y += f3a.y; a3.z += f3b.x; a3.w += f3b.y;
    }
    for (; e < end; e++) {
        int c0 = gPermCol[e];
        uint2 u0 = *(const uint2*)(Ih + (ll)c0 * H + lane * 4);
        float2 f0a = __half22float2(*(__half2*)&u0.x);
        float2 f0b = __half22float2(*(__half2*)&u0.y);
        a0.x += f0a.x; a0.y += f0a.y; a0.z += f0b.x; a0.w += f0b.y;
    }
    float4 a;
    a.x = (a0.x + a1.x) + (a2.x + a3.x);
    a.y = (a0.y + a1.y) + (a2.y + a3.y);
    a.z = (a0.z + a1.z) + (a2.z + a3.z);
    a.w = (a0.w + a1.w) + (a2.w + a3.w);

    const ll NH = (ll)N * H;
    const ll q4 = NH >> 2;
    ll ridx = (ll)r * 32 + lane;

    float4 S  = ((const float4*)gS)[ridx];
    float4 Iv = ((const float4*)gI)[ridx];
    float beta  = __ldg(x + 3 * NH + (ll)r * H + 0);
    float gamma = __ldg(x + 3 * NH + (ll)r * H + 1);

    float4 dS, dI, dR;
    dS.x = -beta * a.x * S.x;  dS.y = -beta * a.y * S.y;
    dS.z = -beta * a.z * S.z;  dS.w = -beta * a.w * S.w;
    dI.x = -dS.x - gamma * Iv.x; dI.y = -dS.y - gamma * Iv.y;
    dI.z = -dS.z - gamma * Iv.z; dI.w = -dS.w - gamma * Iv.w;
    dR.x =  gamma * Iv.x; dR.y = gamma * Iv.y;
    dR.z =  gamma * Iv.z; dR.w = gamma * Iv.w;
    float4 z = make_float4(0.f, 0.f, 0.f, 0.f);

    float4* o4 = (float4*)out;
    o4[ridx]          = dS;
    o4[q4 + ridx]     = dI;
    o4[2 * q4 + ridx] = dR;
    o4[3 * q4 + ridx] = z;
}

// ---------------------------------------------------------------------------
extern "C" void kernel_launch(void* const* d_in, const int* in_sizes, int n_in,
                              void* d_out, int out_size)
{
    const float* x = (const float*)d_in[0];
    const float* W = (const float*)d_in[1];
    const float* b = (const float*)d_in[2];
    const void* rows = d_in[3];
    const void* cols = d_in[4];

    int N = in_sizes[0] / (4 * H);
    ll NE = in_sizes[3];
    int NB = (N + SCAN_BLK - 1) / SCAN_BLK;   // <= 512 for N <= 131072

    transpose_kernel<<<dim3(4, 4), dim3(32, 8)>>>(W);

    int gblocks = (N + 31) / 32;
    gemm_sig_kernel<<<gblocks, 256>>>(x, b, N);

    int N4 = (N + 3) / 4;
    zero_cnt_kernel<<<(N4 + 255) / 256, 256>>>(N4);
    hist_kernel<<<1184, 256>>>(rows, cols, NE);
    scanA_kernel<<<NB, SCAN_BLK>>>(N);
    scanB_kernel<<<1, 512>>>(NB);
    scanC_kernel<<<NB, SCAN_BLK>>>(N);
    scatter_kernel<<<1184, 256>>>(rows, cols, NE);

    gather_epi_kernel<<<(N + 7) / 8, 256>>>(x, (float*)d_out, N);
}

// round 16
// speedup vs baseline: 1.0568x; 1.0568x over previous
#include <cuda_runtime.h>
#include <cuda_fp16.h>

#define H 128
#define NMAX 100000
#define SCAN_BLK 256

// Scratch (alloc-free rule: __device__ globals)
static __device__ float  gS[(size_t)NMAX * H];
static __device__ float  gI[(size_t)NMAX * H];
static __device__ __half gIh[(size_t)NMAX * H];  // fp16 copy of I for gathers
static __device__ float  gWt[H * H];     // W transposed
static __device__ int    gCnt[NMAX];     // per-row edge count
static __device__ int    gStart[NMAX];   // CSR row starts
static __device__ int    gCursor[NMAX];  // scatter cursors
static __device__ int    gBsum[512];     // per-scan-block partial sums
static __device__ int    gBoff[512];     // exclusive-scanned partials
static __device__ int    gPermCol[1700000]; // cols permuted into CSR order

typedef unsigned long long ull;
typedef long long ll;

__device__ __forceinline__ ull pack2(float lo, float hi) {
    ull r; asm("mov.b64 %0, {%1, %2};" : "=l"(r) : "f"(lo), "f"(hi)); return r;
}
__device__ __forceinline__ float2 unpack2(ull v) {
    float2 f; asm("mov.b64 {%0, %1}, %2;" : "=f"(f.x), "=f"(f.y) : "l"(v)); return f;
}
__device__ __forceinline__ ull fma2(ull a, ull b, ull c) {
    ull d; asm("fma.rn.f32x2 %0, %1, %2, %3;" : "=l"(d) : "l"(a), "l"(b), "l"(c)); return d;
}

__device__ __forceinline__ bool idx_is64(const int* r32, const int* c32) {
    // int64 little-endian with values < 2^31: all odd 32-bit words are 0
    return ((r32[1] | r32[3] | r32[5] | c32[1] | c32[3] | c32[5]) == 0);
}

// ---------------------------------------------------------------------------
// Kernel 0: transpose W (128x128) into gWt.
// ---------------------------------------------------------------------------
__global__ void transpose_kernel(const float* __restrict__ W)
{
    __shared__ float tile[32][33];
    int bx = blockIdx.x, by = blockIdx.y;
    int tx = threadIdx.x, ty = threadIdx.y;    // block (32, 8)
    #pragma unroll
    for (int j = 0; j < 4; j++)
        tile[ty + j * 8][tx] = W[(by * 32 + ty + j * 8) * H + bx * 32 + tx];
    __syncthreads();
    #pragma unroll
    for (int j = 0; j < 4; j++)
        gWt[(bx * 32 + ty + j * 8) * H + by * 32 + tx] = tile[tx][ty + j * 8];
}

// ---------------------------------------------------------------------------
// Kernel 0b: zero gCnt (must precede gemm+hist fusion).
// ---------------------------------------------------------------------------
__global__ void zero_cnt_kernel(int N4)   // N4 = ceil(N/4)
{
    int i = blockIdx.x * blockDim.x + threadIdx.x;
    if (i < N4) ((int4*)gCnt)[i] = make_int4(0, 0, 0, 0);
}

// ---------------------------------------------------------------------------
// Kernel 1: S = sigmoid(x0 @ W^T + b), I = sigmoid(x1 @ W^T + b), fp16 copy,
// PLUS fused edge histogram (independent data; rides in the fma-bound
// kernel's memory-pipe slack).  gCnt must be zeroed beforehand.
// ---------------------------------------------------------------------------
__global__ __launch_bounds__(256, 3) void gemm_sig_kernel(
    const float* __restrict__ x, const float* __restrict__ b, int N,
    const void* __restrict__ rows_raw, const void* __restrict__ cols_raw, ll NE)
{
    __shared__ ull xs[32 * H];      // xs[nl*128 + h] = pack(x0[n][h], x1[n][h])

    const int t   = threadIdx.x;
    const int blk = blockIdx.x;
    const ll  NH  = (ll)N * H;

    const int n0 = blk * 32;
    #pragma unroll
    for (int it = 0; it < 4; it++) {
        int idx = t + it * 256;
        int nl = idx >> 5, hq = idx & 31;
        int n = n0 + nl;
        float4 a0 = make_float4(0.f, 0.f, 0.f, 0.f), a1 = a0;
        if (n < N) {
            a0 = *(const float4*)(x + (ll)n * H + hq * 4);
            a1 = *(const float4*)(x + NH + (ll)n * H + hq * 4);
        }
        ull* dst = xs + nl * H + hq * 4;
        dst[0] = pack2(a0.x, a1.x);
        dst[1] = pack2(a0.y, a1.y);
        dst[2] = pack2(a0.z, a1.z);
        dst[3] = pack2(a0.w, a1.w);
    }
    __syncthreads();

    const int to = t & 31;   // output quad: o = 4*to + i
    const int wg = t >> 5;   // node: n = n0 + wg + 8*j

    ull acc[4][4];
    {
        float4 bv = __ldg((const float4*)b + to);
        #pragma unroll
        for (int j = 0; j < 4; j++) {
            acc[j][0] = pack2(bv.x, bv.x);
            acc[j][1] = pack2(bv.y, bv.y);
            acc[j][2] = pack2(bv.z, bv.z);
            acc[j][3] = pack2(bv.w, bv.w);
        }
    }

    const ull* x0p = xs + (wg +  0) * H;
    const ull* x1p = xs + (wg +  8) * H;
    const ull* x2p = xs + (wg + 16) * H;
    const ull* x3p = xs + (wg + 24) * H;
    const float4* wt4 = (const float4*)gWt;

    #pragma unroll 4
    for (int h = 0; h < H; h++) {
        float4 w = __ldg(wt4 + h * 32 + to);
        ull w2[4];
        w2[0] = pack2(w.x, w.x); w2[1] = pack2(w.y, w.y);
        w2[2] = pack2(w.z, w.z); w2[3] = pack2(w.w, w.w);
        ull a0 = x0p[h], a1 = x1p[h], a2 = x2p[h], a3 = x3p[h];
        #pragma unroll
        for (int i = 0; i < 4; i++) {
            acc[0][i] = fma2(a0, w2[i], acc[0][i]);
            acc[1][i] = fma2(a1, w2[i], acc[1][i]);
            acc[2][i] = fma2(a2, w2[i], acc[2][i]);
            acc[3][i] = fma2(a3, w2[i], acc[3][i]);
        }
    }

    #pragma unroll
    for (int j = 0; j < 4; j++) {
        int n = n0 + wg + 8 * j;
        if (n >= N) continue;
        ll rb = (ll)n * H + 4 * to;
        float4 Sv, Iv;
        float2 z0 = unpack2(acc[j][0]);
        float2 z1 = unpack2(acc[j][1]);
        float2 z2 = unpack2(acc[j][2]);
        float2 z3 = unpack2(acc[j][3]);
        Sv.x = 1.f / (1.f + __expf(-z0.x));  Iv.x = 1.f / (1.f + __expf(-z0.y));
        Sv.y = 1.f / (1.f + __expf(-z1.x));  Iv.y = 1.f / (1.f + __expf(-z1.y));
        Sv.z = 1.f / (1.f + __expf(-z2.x));  Iv.z = 1.f / (1.f + __expf(-z2.y));
        Sv.w = 1.f / (1.f + __expf(-z3.x));  Iv.w = 1.f / (1.f + __expf(-z3.y));
        *(float4*)(gS + rb) = Sv;
        *(float4*)(gI + rb) = Iv;
        __half2 p0 = __floats2half2_rn(Iv.x, Iv.y);
        __half2 p1 = __floats2half2_rn(Iv.z, Iv.w);
        uint2 ph;
        ph.x = *(unsigned*)&p0;
        ph.y = *(unsigned*)&p1;
        *(uint2*)(gIh + rb) = ph;
    }

    // --- fused edge histogram (no dependence on the GEMM work above) ---
    {
        const int* r32 = (const int*)rows_raw;
        const ll*  r64 = (const ll*)rows_raw;
        const bool is64 = idx_is64(r32, (const int*)cols_raw);
        ll tid = (ll)blk * 256 + t;
        ll stride = (ll)gridDim.x * 256;
        if (is64) {
            ll nv = NE >> 1;
            const longlong2* rv = (const longlong2*)r64;
            for (ll i = tid; i < nv; i += stride) {
                longlong2 v = __ldg(rv + i);
                atomicAdd(&gCnt[(int)v.x], 1);
                atomicAdd(&gCnt[(int)v.y], 1);
            }
            for (ll e = (nv << 1) + tid; e < NE; e += stride)
                atomicAdd(&gCnt[(int)__ldg(r64 + e)], 1);
        } else {
            ll nv = NE >> 2;
            const int4* rv = (const int4*)r32;
            for (ll i = tid; i < nv; i += stride) {
                int4 v = __ldg(rv + i);
                atomicAdd(&gCnt[v.x], 1);
                atomicAdd(&gCnt[v.y], 1);
                atomicAdd(&gCnt[v.z], 1);
                atomicAdd(&gCnt[v.w], 1);
            }
            for (ll e = (nv << 2) + tid; e < NE; e += stride)
                atomicAdd(&gCnt[__ldg(r32 + e)], 1);
        }
    }
}

// scanA: per-block (256 elems) sum of gCnt -> gBsum
__global__ void scanA_kernel(int N)
{
    __shared__ int sh[SCAN_BLK];
    int i = blockIdx.x * SCAN_BLK + threadIdx.x;
    int v = (i < N) ? gCnt[i] : 0;
    sh[threadIdx.x] = v;
    __syncthreads();
    for (int s = SCAN_BLK / 2; s > 0; s >>= 1) {
        if (threadIdx.x < s) sh[threadIdx.x] += sh[threadIdx.x + s];
        __syncthreads();
    }
    if (threadIdx.x == 0) gBsum[blockIdx.x] = sh[0];
}

// scanB: single block exclusive scan of NB partials
__global__ void scanB_kernel(int NB)
{
    __shared__ int sh[512];
    int t = threadIdx.x;
    sh[t] = (t < NB) ? gBsum[t] : 0;
    __syncthreads();
    for (int d = 1; d < 512; d <<= 1) {
        int v = (t >= d) ? sh[t - d] : 0;
        __syncthreads();
        sh[t] += v;
        __syncthreads();
    }
    if (t < NB) gBoff[t] = sh[t] - gBsum[t];  // exclusive
}

// scanC: per-element exclusive scan within block + block offset
__global__ void scanC_kernel(int N)
{
    __shared__ int sh[SCAN_BLK];
    int t = threadIdx.x;
    int i = blockIdx.x * SCAN_BLK + t;
    int v = (i < N) ? gCnt[i] : 0;
    sh[t] = v;
    __syncthreads();
    for (int d = 1; d < SCAN_BLK; d <<= 1) {
        int u = (t >= d) ? sh[t - d] : 0;
        __syncthreads();
        sh[t] += u;
        __syncthreads();
    }
    if (i < N) {
        int ex = sh[t] - v + gBoff[blockIdx.x];
        gStart[i]  = ex;
        gCursor[i] = ex;
    }
}

__global__ __launch_bounds__(256) void scatter_kernel(
    const void* __restrict__ rows_raw, const void* __restrict__ cols_raw, ll NE)
{
    const int* r32 = (const int*)rows_raw;
    const int* c32 = (const int*)cols_raw;
    const ll*  r64 = (const ll*)rows_raw;
    const ll*  c64 = (const ll*)cols_raw;
    const bool is64 = idx_is64(r32, c32);
    ll tid = (ll)blockIdx.x * blockDim.x + threadIdx.x;
    ll stride = (ll)gridDim.x * blockDim.x;
    if (is64) {
        ll nv = NE >> 1;
        const longlong2* rv = (const longlong2*)r64;
        const longlong2* cv = (const longlong2*)c64;
        for (ll i = tid; i < nv; i += stride) {
            longlong2 r = __ldg(rv + i);
            longlong2 c = __ldg(cv + i);
            gPermCol[atomicAdd(&gCursor[(int)r.x], 1)] = (int)c.x;
            gPermCol[atomicAdd(&gCursor[(int)r.y], 1)] = (int)c.y;
        }
        for (ll e = (nv << 1) + tid; e < NE; e += stride)
            gPermCol[atomicAdd(&gCursor[(int)__ldg(r64 + e)], 1)] = (int)__ldg(c64 + e);
    } else {
        ll nv = NE >> 2;
        const int4* rv = (const int4*)r32;
        const int4* cv = (const int4*)c32;
        for (ll i = tid; i < nv; i += stride) {
            int4 r = __ldg(rv + i);
            int4 c = __ldg(cv + i);
            gPermCol[atomicAdd(&gCursor[r.x], 1)] = c.x;
            gPermCol[atomicAdd(&gCursor[r.y], 1)] = c.y;
            gPermCol[atomicAdd(&gCursor[r.z], 1)] = c.z;
            gPermCol[atomicAdd(&gCursor[r.w], 1)] = c.w;
        }
        for (ll e = (nv << 2) + tid; e < NE; e += stride)
            gPermCol[atomicAdd(&gCursor[__ldg(r32 + e)], 1)] = __ldg(c32 + e);
    }
}

// ---------------------------------------------------------------------------
// Fused gather + epilogue (round-14 proven form).  Warp per row r:
//   AI = sum_{e in CSR[r]} Ih[col[e]]  (fp16 gather, fp32 accumulate)
//   dS = -beta*AI*S; dI = -dS - gamma*I; dR = gamma*I; out[3] = 0.
// ---------------------------------------------------------------------------
__global__ __launch_bounds__(256) void gather_epi_kernel(
    const float* __restrict__ x, float* __restrict__ out, int N)
{
    int warp = (blockIdx.x * 256 + threadIdx.x) >> 5;
    int lane = threadIdx.x & 31;
    if (warp >= N) return;
    const int r = warp;

    int start = gStart[r];
    int end   = start + gCnt[r];

    // lane handles values [lane*4, lane*4+4): 8 bytes of fp16 per row
    const __half* Ih = gIh;
    float4 a = make_float4(0.f, 0.f, 0.f, 0.f);
    float4 bacc = a;

    int e = start;
    for (; e + 1 < end; e += 2) {
        int c0 = gPermCol[e];
        int c1 = gPermCol[e + 1];
        uint2 u0 = *(const uint2*)(Ih + (ll)c0 * H + lane * 4);
        uint2 u1 = *(const uint2*)(Ih + (ll)c1 * H + lane * 4);
        float2 f0 = __half22float2(*(__half2*)&u0.x);
        float2 f1 = __half22float2(*(__half2*)&u0.y);
        float2 f2 = __half22float2(*(__half2*)&u1.x);
        float2 f3 = __half22float2(*(__half2*)&u1.y);
        a.x += f0.x; a.y += f0.y; a.z += f1.x; a.w += f1.y;
        bacc.x += f2.x; bacc.y += f2.y; bacc.z += f3.x; bacc.w += f3.y;
    }
    if (e < end) {
        int c0 = gPermCol[e];
        uint2 u0 = *(const uint2*)(Ih + (ll)c0 * H + lane * 4);
        float2 f0 = __half22float2(*(__half2*)&u0.x);
        float2 f1 = __half22float2(*(__half2*)&u0.y);
        a.x += f0.x; a.y += f0.y; a.z += f1.x; a.w += f1.y;
    }
    a.x += bacc.x; a.y += bacc.y; a.z += bacc.z; a.w += bacc.w;

    const ll NH = (ll)N * H;
    const ll q4 = NH >> 2;
    ll ridx = (ll)r * 32 + lane;

    float4 S  = ((const float4*)gS)[ridx];
    float4 Iv = ((const float4*)gI)[ridx];
    float beta  = __ldg(x + 3 * NH + (ll)r * H + 0);
    float gamma = __ldg(x + 3 * NH + (ll)r * H + 1);

    float4 dS, dI, dR;
    dS.x = -beta * a.x * S.x;  dS.y = -beta * a.y * S.y;
    dS.z = -beta * a.z * S.z;  dS.w = -beta * a.w * S.w;
    dI.x = -dS.x - gamma * Iv.x; dI.y = -dS.y - gamma * Iv.y;
    dI.z = -dS.z - gamma * Iv.z; dI.w = -dS.w - gamma * Iv.w;
    dR.x =  gamma * Iv.x; dR.y = gamma * Iv.y;
    dR.z =  gamma * Iv.z; dR.w = gamma * Iv.w;
    float4 z = make_float4(0.f, 0.f, 0.f, 0.f);

    float4* o4 = (float4*)out;
    o4[ridx]          = dS;
    o4[q4 + ridx]     = dI;
    o4[2 * q4 + ridx] = dR;
    o4[3 * q4 + ridx] = z;
}

// ---------------------------------------------------------------------------
extern "C" void kernel_launch(void* const* d_in, const int* in_sizes, int n_in,
                              void* d_out, int out_size)
{
    const float* x = (const float*)d_in[0];
    const float* W = (const float*)d_in[1];
    const float* b = (const float*)d_in[2];
    const void* rows = d_in[3];
    const void* cols = d_in[4];

    int N = in_sizes[0] / (4 * H);
    ll NE = in_sizes[3];
    int NB = (N + SCAN_BLK - 1) / SCAN_BLK;   // <= 512 for N <= 131072

    transpose_kernel<<<dim3(4, 4), dim3(32, 8)>>>(W);

    int N4 = (N + 3) / 4;
    zero_cnt_kernel<<<(N4 + 255) / 256, 256>>>(N4);

    int gblocks = (N + 31) / 32;
    gemm_sig_kernel<<<gblocks, 256>>>(x, b, N, rows, cols, NE);

    scanA_kernel<<<NB, SCAN_BLK>>>(N);
    scanB_kernel<<<1, 512>>>(NB);
    scanC_kernel<<<NB, SCAN_BLK>>>(N);
    scatter_kernel<<<1184, 256>>>(rows, cols, NE);

    gather_epi_kernel<<<(N + 7) / 8, 256>>>(x, (float*)d_out, N);
}